// round 14
// baseline (speedup 1.0000x reference)
#include <cuda_runtime.h>
#include <cuda_bf16.h>
#include <cstdint>

#define B_SAMP 256
#define C_CLS  65536
#define D_DIM  2048
#define NCAM   8
#define CAP    12288
#define INV_TEMP 14.285714285714286f

#define TILE_N 64
#define TILE_M 64
#define TILE_K 64
#define NKT    (D_DIM / TILE_K)
#define GEMM_TILE_MAX 1032
#define GEMM_BLOCKS (GEMM_TILE_MAX + B_SAMP)
#define PREP_BLOCKS 64

// dynamic smem layout: [0,16K) smA[2]; [16K,32K) smB[2]; [32K,64K) fp32 staging[2]
#define OFF_A   0
#define OFF_B   16384
#define OFF_STG 32768
#define GEMM_SMEM 65536

// ---------------- device scratch ----------------
__device__ float g_sumexp[B_SAMP];
__device__ float g_pos[B_SAMP];
__device__ int   g_perm[NCAM * CAP];
__device__ int   g_samp[NCAM * B_SAMP];
__device__ int   g_samp_cnt[NCAM];
__device__ int   g_tile_base[NCAM + 1];
__device__ int   g_blkcnt[PREP_BLOCKS * NCAM];
__device__ int   g_done;
__device__ unsigned char g_is_label[C_CLS];
__device__ __align__(16) __nv_bfloat16 g_featb[B_SAMP * D_DIM];

// ---------------- helpers ----------------
__device__ __forceinline__ uint32_t smem_u32(const void* p) {
    return (uint32_t)__cvta_generic_to_shared(p);
}
__device__ __forceinline__ void cp_async16(uint32_t dst, const void* src) {
    asm volatile("cp.async.ca.shared.global [%0], [%1], 16;" :: "r"(dst), "l"(src));
}
__device__ __forceinline__ void cp_async16_cg(uint32_t dst, const void* src) {
    asm volatile("cp.async.cg.shared.global [%0], [%1], 16;" :: "r"(dst), "l"(src));
}
__device__ __forceinline__ void cp_commit() {
    asm volatile("cp.async.commit_group;");
}
__device__ __forceinline__ void cp_wait1() {
    asm volatile("cp.async.wait_group 1;");
}
__device__ __forceinline__ void lds128_f(float4& v, uint32_t addr) {
    asm volatile("ld.shared.v4.f32 {%0,%1,%2,%3}, [%4];"
                 : "=f"(v.x), "=f"(v.y), "=f"(v.z), "=f"(v.w) : "r"(addr));
}
__device__ __forceinline__ void ldsm_x4(uint32_t& r0, uint32_t& r1, uint32_t& r2, uint32_t& r3,
                                        uint32_t addr) {
    asm volatile("ldmatrix.sync.aligned.m8n8.x4.shared.b16 {%0,%1,%2,%3}, [%4];"
                 : "=r"(r0), "=r"(r1), "=r"(r2), "=r"(r3) : "r"(addr));
}
__device__ __forceinline__ void mma_bf16(float& c0, float& c1, float& c2, float& c3,
                                         uint32_t a0, uint32_t a1, uint32_t a2, uint32_t a3,
                                         uint32_t b0, uint32_t b1) {
    asm volatile(
        "mma.sync.aligned.m16n8k16.row.col.f32.bf16.bf16.f32 "
        "{%0,%1,%2,%3}, {%4,%5,%6,%7}, {%8,%9}, {%0,%1,%2,%3};"
        : "+f"(c0), "+f"(c1), "+f"(c2), "+f"(c3)
        : "r"(a0), "r"(a1), "r"(a2), "r"(a3), "r"(b0), "r"(b1));
}
// packed pair: result lo = a, hi = b (single cvt instruction)
__device__ __forceinline__ uint32_t bf2_bits(float a, float b) {
    uint32_t r;
    asm("cvt.rn.bf16x2.f32 %0, %1, %2;" : "=r"(r) : "f"(b), "f"(a));
    return r;
}
__device__ __forceinline__ void sts64(uint32_t addr, uint32_t a, uint32_t b) {
    asm volatile("st.shared.v2.b32 [%0], {%1,%2};" :: "r"(addr), "r"(a), "r"(b));
}
__device__ __forceinline__ uint32_t sw128(uint32_t o) { return o ^ ((o >> 3) & 0x70u); }

// ---------------- prep0: feat fp32->bf16 + camera histogram + clears ----------------
__global__ void prep0_kernel(const float* __restrict__ f,
                             const int* __restrict__ class_camera) {
    int tid = threadIdx.x;
    int i = blockIdx.x * blockDim.x + tid;           // 512 blocks x 256
    float4 v = ((const float4*)f)[i];
    ((uint2*)g_featb)[i] = make_uint2(bf2_bits(v.x, v.y), bf2_bits(v.z, v.w));

    if (blockIdx.x == 0 && tid == 0) g_done = 0;
    if (blockIdx.x < PREP_BLOCKS) {
        ((int*)g_is_label)[blockIdx.x * 256 + tid] = 0;
        __shared__ int h[NCAM];
        if (tid < NCAM) h[tid] = 0;
        __syncthreads();
        int4 c4 = ((const int4*)class_camera)[blockIdx.x * 256 + tid];
        atomicAdd(&h[c4.x], 1); atomicAdd(&h[c4.y], 1);
        atomicAdd(&h[c4.z], 1); atomicAdd(&h[c4.w], 1);
        __syncthreads();
        if (tid < NCAM) g_blkcnt[blockIdx.x * NCAM + tid] = h[tid];
    }
}

// ---------------- prep13: scatter + grouping/tile bases/label map ----------------
__global__ void prep13_kernel(const int* __restrict__ class_camera,
                              const int* __restrict__ cams,
                              const int* __restrict__ labels) {
    int tid = threadIdx.x;
    if (blockIdx.x < PREP_BLOCKS) {
        __shared__ int off[NCAM];
        if (tid < NCAM) {
            int base = 0;
            for (int b2 = 0; b2 < blockIdx.x; b2++)
                base += g_blkcnt[b2 * NCAM + tid];
            off[tid] = base;
        }
        __syncthreads();
        int base = blockIdx.x * 1024 + tid * 4;
        int4 c4 = ((const int4*)class_camera)[blockIdx.x * 256 + tid];
        int p;
        p = atomicAdd(&off[c4.x], 1); g_perm[c4.x * CAP + p] = base + 0;
        p = atomicAdd(&off[c4.y], 1); g_perm[c4.y * CAP + p] = base + 1;
        p = atomicAdd(&off[c4.z], 1); g_perm[c4.z * CAP + p] = base + 2;
        p = atomicAdd(&off[c4.w], 1); g_perm[c4.w * CAP + p] = base + 3;
    } else {
        __shared__ int scnt[NCAM];
        __shared__ int ssnt[NCAM];
        if (tid < B_SAMP) { g_sumexp[tid] = 0.f; g_pos[tid] = 0.f; }
        g_is_label[labels[tid]] = 1;
        if (tid < NCAM) ssnt[tid] = 0;
        if (tid < NCAM) {
            int base = 0;
            for (int b2 = 0; b2 < PREP_BLOCKS; b2++)
                base += g_blkcnt[b2 * NCAM + tid];
            scnt[tid] = base;
            int pad = (base + 63) & ~63;
            for (int s = base; s < pad; s++) g_perm[tid * CAP + s] = -1;
        }
        __syncthreads();
        {
            int c = cams[tid];
            int p = atomicAdd(&ssnt[c], 1);
            g_samp[c * B_SAMP + p] = tid;
        }
        __syncthreads();
        if (tid < NCAM) g_samp_cnt[tid] = ssnt[tid];
        if (tid == 0) {
            int tb = 0;
            for (int c = 0; c < NCAM; c++) {
                g_tile_base[c] = tb;
                tb += (scnt[c] + 63) >> 6;
            }
            g_tile_base[NCAM] = tb;
        }
    }
}

// ---------------- sequential EMA per label chain (device fn, runs in gemm grid) ----------------
__device__ void ema_block(int b, const float* __restrict__ mem,
                          const float* __restrict__ feat,
                          const int* __restrict__ labels,
                          float* __restrict__ out_mem) {
    __shared__ int s_labels[B_SAMP];
    __shared__ float wsum[8];
    int t = threadIdx.x;
    s_labels[t] = labels[t];
    __syncthreads();

    int y = s_labels[b];
    for (int j = b + 1; j < B_SAMP; j++)
        if (s_labels[j] == y) return;        // only last occurrence owns the chain
    int lane = t & 31, wid = t >> 5;
    float r[8];
    const float* m = mem + (size_t)y * D_DIM;
#pragma unroll
    for (int i = 0; i < 8; i++) r[i] = m[t + i * 256];
    for (int j = 0; j < B_SAMP; j++) {
        if (s_labels[j] != y) continue;
        const float* x = feat + (size_t)j * D_DIM;
        float ss = 0.f;
#pragma unroll
        for (int i = 0; i < 8; i++) {
            r[i] = 0.2f * r[i] + 0.8f * x[t + i * 256];
            ss += r[i] * r[i];
        }
#pragma unroll
        for (int o = 16; o > 0; o >>= 1) ss += __shfl_xor_sync(0xffffffffu, ss, o);
        if (lane == 0) wsum[wid] = ss;
        __syncthreads();
        float tot = wsum[0] + wsum[1] + wsum[2] + wsum[3]
                  + wsum[4] + wsum[5] + wsum[6] + wsum[7];
        float rinv = rsqrtf(tot);
        __syncthreads();
#pragma unroll
        for (int i = 0; i < 8; i++) r[i] *= rinv;
    }
    float* o = out_mem + (size_t)y * D_DIM;
#pragma unroll
    for (int i = 0; i < 8; i++) o[t + i * 256] = r[i];
}

// ---------------- fused GEMM + copy + exp reduce + EMA overlap + final loss ----------------
// B now flows gmem -> cp.async.cg -> fp32 smem staging -> (own-thread) LDS+cvt ->
// smB bf16 + copy-out. No DRAM-latency load on the register critical path.
__global__ __launch_bounds__(256, 3) void gemm_kernel(const float* __restrict__ mem,
                                                      const int* __restrict__ labels,
                                                      const float* __restrict__ feat,
                                                      const int* __restrict__ cams,
                                                      float* __restrict__ out_mem) {
    extern __shared__ unsigned char dsm[];
    int b = blockIdx.x;
    int tid = threadIdx.x;
    if (b >= GEMM_TILE_MAX) {
        ema_block(b - GEMM_TILE_MAX, mem, feat, labels, out_mem);
        return;
    }

    if (b < g_tile_base[NCAM]) {
        int cam = 0;
        while (b >= g_tile_base[cam + 1]) cam++;
        int tile = b - g_tile_base[cam];

        __shared__ int s_cls[TILE_N];
        __shared__ int s_samp[TILE_M];
        __shared__ int s_lab[TILE_M];

        int w = tid >> 5, L = tid & 31;
        int mi = w & 3, ni = w >> 2;

        if (tid < TILE_N) s_cls[tid] = g_perm[cam * CAP + tile * TILE_N + tid];
        int ncs = g_samp_cnt[cam];
        int nch = max(1, (ncs + TILE_M - 1) / TILE_M);   // == 1 in practice
        __syncthreads();

        // B: row-contiguous mapping. col4 = tid&15, rows = (tid>>4) + 16j.
        int col4 = tid & 15;
        int rb   = tid >> 4;
        const float* bsrc[4];
        bool bcopy[4];
        uint32_t stg_off[4];          // thread-private staging offsets (unswizzled)
#pragma unroll
        for (int j = 0; j < 4; j++) {
            int row = rb + 16 * j;
            int cls = s_cls[row];
            bsrc[j] = mem + (size_t)(cls >= 0 ? cls : 0) * D_DIM + col4 * 4;
            bcopy[j] = (cls >= 0) && (g_is_label[cls >= 0 ? cls : 0] == 0);
            stg_off[j] = (uint32_t)(row * 256 + col4 * 16);
        }
        const ptrdiff_t out_off = out_mem - mem;
        uint32_t sbso = sw128((uint32_t)(rb * 128 + col4 * 8));

        // A: 4 threads/row, 32B each (2x cp.async 16B)
        int arow = tid >> 2;
        int ach  = tid & 3;
        uint32_t saso = sw128((uint32_t)(arow * 128 + ach * 32));

        uint32_t smA_u[2] = { smem_u32(dsm + OFF_A), smem_u32(dsm + OFF_A + 8192) };
        uint32_t smB_u[2] = { smem_u32(dsm + OFF_B), smem_u32(dsm + OFF_B + 8192) };
        uint32_t stg_u[2] = { smem_u32(dsm + OFF_STG), smem_u32(dsm + OFF_STG + 16384) };

        for (int mc = 0; mc < nch; mc++) {
            if (tid < TILE_M) {
                int m = mc * TILE_M + tid;
                int s = (m < ncs) ? g_samp[cam * B_SAMP + m] : -1;
                s_samp[tid] = s;
                s_lab[tid]  = (s >= 0) ? labels[s] : -1;
            }
            __syncthreads();
            int samp = s_samp[arow];
            const __nv_bfloat16* asrcg =
                g_featb + (size_t)(samp >= 0 ? samp : 0) * D_DIM + ach * 16;

            float acc[16];
#pragma unroll
            for (int i = 0; i < 16; i++) acc[i] = 0.f;

            // prologue: group P0 = {A(0), B(0)}, group P1 = {B(1)}
            cp_async16(smA_u[0] + saso, asrcg);
            cp_async16(smA_u[0] + (saso ^ 16u), asrcg + 8);
#pragma unroll
            for (int j = 0; j < 4; j++)
                cp_async16_cg(stg_u[0] + stg_off[j], bsrc[j]);
            cp_commit();
#pragma unroll
            for (int j = 0; j < 4; j++)
                cp_async16_cg(stg_u[1] + stg_off[j], bsrc[j] + TILE_K);
            cp_commit();

            bool do_copy = (mc == 0);
            float carry[4] = {0.f, 0.f, 0.f, 0.f};
            for (int kt = 0; kt < NKT; kt++) {
                int buf = kt & 1;
                cp_wait1();     // all but newest group done => A(kt), B(kt) ready
                // ---- convert own staged fp32 -> smB bf16, + carry copy-out
#pragma unroll
                for (int j = 0; j < 4; j++) {
                    float4 v;
                    lds128_f(v, stg_u[buf] + stg_off[j]);
                    sts64(smB_u[buf] + sbso + (uint32_t)(j * 2048),
                          bf2_bits(v.x, v.y), bf2_bits(v.z, v.w));
                    if (do_copy) {
                        float up = __shfl_up_sync(0xffffffffu, v.w, 1);
                        float nc = __shfl_sync(0xffffffffu, v.w, L | 15);
                        if (bcopy[j]) {
                            float* dst = (float*)(bsrc[j] + out_off) + kt * TILE_K;
                            if (kt == 0 && col4 == 0) {
                                dst[0] = v.x; dst[1] = v.y; dst[2] = v.z;
                            } else {
                                float lead = (col4 == 0) ? carry[j] : up;
                                *(float4*)(dst - 1) = make_float4(lead, v.x, v.y, v.z);
                            }
                            if (kt == NKT - 1 && col4 == 15) dst[3] = v.w;
                        }
                        carry[j] = nc;
                    }
                }
                __syncthreads();
                // ---- issue next stages (A older group, B newest group — always commit)
                if (kt < NKT - 1) {
                    int ko = (kt + 1) * TILE_K;
                    cp_async16(smA_u[buf ^ 1] + saso, asrcg + ko);
                    cp_async16(smA_u[buf ^ 1] + (saso ^ 16u), asrcg + ko + 8);
                }
                cp_commit();
                if (kt < NKT - 2) {
                    int ko = (kt + 2) * TILE_K;
#pragma unroll
                    for (int j = 0; j < 4; j++)
                        cp_async16_cg(stg_u[buf] + stg_off[j], bsrc[j] + ko);
                }
                cp_commit();
                // ---- mma on smem[buf]: warp computes m16 x n32
                {
                    uint32_t arw = (uint32_t)(mi * 16 + (L & 15));
                    uint32_t kh  = (uint32_t)(L >> 4) * 16u;
#pragma unroll
                    for (int ks = 0; ks < 4; ks++) {
                        uint32_t acol = (uint32_t)(ks * 32) + kh;
                        uint32_t ao = sw128(arw * 128 + acol);
                        uint32_t a0, a1, a2, a3;
                        ldsm_x4(a0, a1, a2, a3, smA_u[buf] + ao);
#pragma unroll
                        for (int bh = 0; bh < 2; bh++) {
                            uint32_t brw = (uint32_t)(ni * 32 + bh * 16 + (L & 15));
                            uint32_t bo = sw128(brw * 128 + acol);
                            uint32_t b0, b1, b2, b3;
                            ldsm_x4(b0, b1, b2, b3, smB_u[buf] + bo);
                            float* aB = acc + bh * 8;
                            mma_bf16(aB[0], aB[1], aB[2], aB[3], a0, a1, a2, a3, b0, b2);
                            mma_bf16(aB[4], aB[5], aB[6], aB[7], a0, a1, a2, a3, b1, b3);
                        }
                    }
                }
            }

            // ---- epilogue: scale, exp, pos capture, row reduce (validated)
            {
                int rlo = mi * 16 + (L >> 2);
                int rhi = rlo + 8;
                int slo_s = s_samp[rlo], shi_s = s_samp[rhi];
                int llo = s_lab[rlo],    lhi = s_lab[rhi];
                float slo = 0.f, shi = 0.f;
#pragma unroll
                for (int t = 0; t < 4; t++) {
                    int cbase = ni * 32 + t * 8 + (L & 3) * 2;
#pragma unroll
                    for (int c = 0; c < 2; c++) {
                        int cls = s_cls[cbase + c];
                        if (cls >= 0) {
                            if (slo_s >= 0) {
                                float val = acc[t * 4 + c] * INV_TEMP;
                                slo += __expf(val);
                                if (cls == llo) g_pos[slo_s] = val;
                            }
                            if (shi_s >= 0) {
                                float val = acc[t * 4 + 2 + c] * INV_TEMP;
                                shi += __expf(val);
                                if (cls == lhi) g_pos[shi_s] = val;
                            }
                        }
                    }
                }
                slo += __shfl_xor_sync(0xffffffffu, slo, 1);
                slo += __shfl_xor_sync(0xffffffffu, slo, 2);
                shi += __shfl_xor_sync(0xffffffffu, shi, 1);
                shi += __shfl_xor_sync(0xffffffffu, shi, 2);
                if ((L & 3) == 0) {
                    if (slo_s >= 0) atomicAdd(&g_sumexp[slo_s], slo);
                    if (shi_s >= 0) atomicAdd(&g_sumexp[shi_s], shi);
                }
            }
            __syncthreads();
        }
    }

    // ---- completion signal; last tile-slot block computes the loss ----
    __threadfence();
    __shared__ int s_last;
    if (tid == 0) s_last = (atomicAdd(&g_done, 1) == GEMM_TILE_MAX - 1) ? 1 : 0;
    __syncthreads();
    if (s_last) {
        __threadfence();
        __shared__ float red[256];
        float v = (logf(g_sumexp[tid]) - g_pos[tid]) / (float)g_samp_cnt[cams[tid]];
        red[tid] = v;
        __syncthreads();
        for (int s = 128; s > 0; s >>= 1) {
            if (tid < s) red[tid] += red[tid + s];
            __syncthreads();
        }
        if (tid == 0) out_mem[-1] = red[0];   // out[0] = loss
    }
}

extern "C" void kernel_launch(void* const* d_in, const int* in_sizes, int n_in,
                              void* d_out, int out_size) {
    const float* features     = (const float*)d_in[0];
    const int*   labels       = (const int*)d_in[1];
    const int*   cams         = (const int*)d_in[2];
    const float* class_memory = (const float*)d_in[3];
    const int*   class_camera = (const int*)d_in[4];
    float* out = (float*)d_out;          // [0] = loss, [1..] = new_memory
    float* out_mem = out + 1;

    cudaFuncSetAttribute(gemm_kernel, cudaFuncAttributeMaxDynamicSharedMemorySize,
                         GEMM_SMEM);

    prep0_kernel<<<512, 256>>>(features, class_camera);                  // slot 0
    prep13_kernel<<<PREP_BLOCKS + 1, 256>>>(class_camera, cams, labels); // slot 1
    gemm_kernel<<<GEMM_BLOCKS, 256, GEMM_SMEM>>>(class_memory, labels, features,
                                                 cams, out_mem);         // slot 2
}

// round 15
// speedup vs baseline: 1.1114x; 1.1114x over previous
#include <cuda_runtime.h>
#include <cuda_bf16.h>
#include <cstdint>

#define B_SAMP 256
#define C_CLS  65536
#define D_DIM  2048
#define NCAM   8
#define CAP    12288
#define INV_TEMP 14.285714285714286f

#define TILE_N 64
#define TILE_M 64
#define TILE_K 64
#define NKT    (D_DIM / TILE_K)
#define GEMM_TILE_MAX 1032
#define GEMM_BLOCKS (GEMM_TILE_MAX + B_SAMP)
#define PREP_BLOCKS 64

// ---------------- device scratch ----------------
__device__ float g_sumexp[B_SAMP];
__device__ float g_pos[B_SAMP];
__device__ int   g_perm[NCAM * CAP];
__device__ int   g_samp[NCAM * B_SAMP];
__device__ int   g_samp_cnt[NCAM];
__device__ int   g_tile_base[NCAM + 1];
__device__ int   g_blkcnt[PREP_BLOCKS * NCAM];
__device__ int   g_done;
__device__ unsigned char g_is_label[C_CLS];
__device__ __align__(16) __nv_bfloat16 g_featb[B_SAMP * D_DIM];

// ---------------- helpers ----------------
__device__ __forceinline__ uint32_t smem_u32(const void* p) {
    return (uint32_t)__cvta_generic_to_shared(p);
}
__device__ __forceinline__ void cp_async16(uint32_t dst, const void* src) {
    asm volatile("cp.async.ca.shared.global [%0], [%1], 16;" :: "r"(dst), "l"(src));
}
__device__ __forceinline__ void cp_commit() {
    asm volatile("cp.async.commit_group;");
}
__device__ __forceinline__ void cp_wait0() {
    asm volatile("cp.async.wait_group 0;");
}
__device__ __forceinline__ void ldsm_x4(uint32_t& r0, uint32_t& r1, uint32_t& r2, uint32_t& r3,
                                        uint32_t addr) {
    asm volatile("ldmatrix.sync.aligned.m8n8.x4.shared.b16 {%0,%1,%2,%3}, [%4];"
                 : "=r"(r0), "=r"(r1), "=r"(r2), "=r"(r3) : "r"(addr));
}
__device__ __forceinline__ void mma_bf16(float& c0, float& c1, float& c2, float& c3,
                                         uint32_t a0, uint32_t a1, uint32_t a2, uint32_t a3,
                                         uint32_t b0, uint32_t b1) {
    asm volatile(
        "mma.sync.aligned.m16n8k16.row.col.f32.bf16.bf16.f32 "
        "{%0,%1,%2,%3}, {%4,%5,%6,%7}, {%8,%9}, {%0,%1,%2,%3};"
        : "+f"(c0), "+f"(c1), "+f"(c2), "+f"(c3)
        : "r"(a0), "r"(a1), "r"(a2), "r"(a3), "r"(b0), "r"(b1));
}
// packed pair: result lo = a, hi = b (single cvt instruction)
__device__ __forceinline__ uint32_t bf2_bits(float a, float b) {
    uint32_t r;
    asm("cvt.rn.bf16x2.f32 %0, %1, %2;" : "=r"(r) : "f"(b), "f"(a));
    return r;
}
__device__ __forceinline__ uint32_t sw128(uint32_t o) { return o ^ ((o >> 3) & 0x70u); }

// ---------------- prep0: feat fp32->bf16 + camera histogram + clears ----------------
__global__ void prep0_kernel(const float* __restrict__ f,
                             const int* __restrict__ class_camera) {
    int tid = threadIdx.x;
    int i = blockIdx.x * blockDim.x + tid;           // 512 blocks x 256
    float4 v = ((const float4*)f)[i];
    ((uint2*)g_featb)[i] = make_uint2(bf2_bits(v.x, v.y), bf2_bits(v.z, v.w));

    if (blockIdx.x == 0 && tid == 0) g_done = 0;
    if (blockIdx.x < PREP_BLOCKS) {
        // clear is_label (64 blocks x 256 threads x 4B = 64KB)
        ((int*)g_is_label)[blockIdx.x * 256 + tid] = 0;
        __shared__ int h[NCAM];
        if (tid < NCAM) h[tid] = 0;
        __syncthreads();
        int4 c4 = ((const int4*)class_camera)[blockIdx.x * 256 + tid];
        atomicAdd(&h[c4.x], 1); atomicAdd(&h[c4.y], 1);
        atomicAdd(&h[c4.z], 1); atomicAdd(&h[c4.w], 1);
        __syncthreads();
        if (tid < NCAM) g_blkcnt[blockIdx.x * NCAM + tid] = h[tid];
    }
}

// ---------------- prep13: scatter (blocks 0-63, self-computed prefix)
//                  + grouping/tile bases/label map (block 64) ----------------
__global__ void prep13_kernel(const int* __restrict__ class_camera,
                              const int* __restrict__ cams,
                              const int* __restrict__ labels) {
    int tid = threadIdx.x;
    if (blockIdx.x < PREP_BLOCKS) {
        __shared__ int off[NCAM];
        if (tid < NCAM) {
            int base = 0;
            for (int b2 = 0; b2 < blockIdx.x; b2++)
                base += g_blkcnt[b2 * NCAM + tid];
            off[tid] = base;
        }
        __syncthreads();
        int base = blockIdx.x * 1024 + tid * 4;
        int4 c4 = ((const int4*)class_camera)[blockIdx.x * 256 + tid];
        int p;
        p = atomicAdd(&off[c4.x], 1); g_perm[c4.x * CAP + p] = base + 0;
        p = atomicAdd(&off[c4.y], 1); g_perm[c4.y * CAP + p] = base + 1;
        p = atomicAdd(&off[c4.z], 1); g_perm[c4.z * CAP + p] = base + 2;
        p = atomicAdd(&off[c4.w], 1); g_perm[c4.w * CAP + p] = base + 3;
    } else {
        // old prep2 work (minus blkbase, now unneeded)
        __shared__ int scnt[NCAM];
        __shared__ int ssnt[NCAM];
        if (tid < B_SAMP) { g_sumexp[tid] = 0.f; g_pos[tid] = 0.f; }
        g_is_label[labels[tid]] = 1;
        if (tid < NCAM) ssnt[tid] = 0;
        if (tid < NCAM) {
            int base = 0;
            for (int b2 = 0; b2 < PREP_BLOCKS; b2++)
                base += g_blkcnt[b2 * NCAM + tid];
            scnt[tid] = base;
            int pad = (base + 63) & ~63;
            for (int s = base; s < pad; s++) g_perm[tid * CAP + s] = -1;
        }
        __syncthreads();
        {
            int c = cams[tid];
            int p = atomicAdd(&ssnt[c], 1);
            g_samp[c * B_SAMP + p] = tid;
        }
        __syncthreads();
        if (tid < NCAM) g_samp_cnt[tid] = ssnt[tid];
        if (tid == 0) {
            int tb = 0;
            for (int c = 0; c < NCAM; c++) {
                g_tile_base[c] = tb;
                tb += (scnt[c] + 63) >> 6;
            }
            g_tile_base[NCAM] = tb;
        }
    }
}

// ---------------- sequential EMA per label chain (device fn, runs in gemm grid) ----------------
__device__ void ema_block(int b, const float* __restrict__ mem,
                          const float* __restrict__ feat,
                          const int* __restrict__ labels,
                          float* __restrict__ out_mem) {
    __shared__ int s_labels[B_SAMP];
    __shared__ float wsum[8];
    int t = threadIdx.x;
    s_labels[t] = labels[t];
    __syncthreads();

    int y = s_labels[b];
    for (int j = b + 1; j < B_SAMP; j++)
        if (s_labels[j] == y) return;        // only last occurrence owns the chain
    int lane = t & 31, wid = t >> 5;
    float r[8];
    const float* m = mem + (size_t)y * D_DIM;
#pragma unroll
    for (int i = 0; i < 8; i++) r[i] = m[t + i * 256];
    for (int j = 0; j < B_SAMP; j++) {
        if (s_labels[j] != y) continue;
        const float* x = feat + (size_t)j * D_DIM;
        float ss = 0.f;
#pragma unroll
        for (int i = 0; i < 8; i++) {
            r[i] = 0.2f * r[i] + 0.8f * x[t + i * 256];
            ss += r[i] * r[i];
        }
#pragma unroll
        for (int o = 16; o > 0; o >>= 1) ss += __shfl_xor_sync(0xffffffffu, ss, o);
        if (lane == 0) wsum[wid] = ss;
        __syncthreads();
        float tot = wsum[0] + wsum[1] + wsum[2] + wsum[3]
                  + wsum[4] + wsum[5] + wsum[6] + wsum[7];
        float rinv = rsqrtf(tot);
        __syncthreads();
#pragma unroll
        for (int i = 0; i < 8; i++) r[i] *= rinv;
    }
    float* o = out_mem + (size_t)y * D_DIM;
#pragma unroll
    for (int i = 0; i < 8; i++) o[t + i * 256] = r[i];
}

// ---------------- fused GEMM + copy + exp reduce + EMA overlap + final loss ----------------
// r11 gemm loop frozen. Last tile-slot block to finish runs the loss reduction.
__global__ __launch_bounds__(256, 3) void gemm_kernel(const float* __restrict__ mem,
                                                      const int* __restrict__ labels,
                                                      const float* __restrict__ feat,
                                                      const int* __restrict__ cams,
                                                      float* __restrict__ out_mem) {
    int b = blockIdx.x;
    int tid = threadIdx.x;
    if (b >= GEMM_TILE_MAX) {
        ema_block(b - GEMM_TILE_MAX, mem, feat, labels, out_mem);
        return;
    }

    if (b < g_tile_base[NCAM]) {
        int cam = 0;
        while (b >= g_tile_base[cam + 1]) cam++;
        int tile = b - g_tile_base[cam];

        __shared__ int s_cls[TILE_N];
        __shared__ int s_samp[TILE_M];
        __shared__ int s_lab[TILE_M];
        __shared__ __align__(16) unsigned char smA[2][TILE_M * 128];  // 64 x 64 bf16
        __shared__ __align__(16) unsigned char smB[2][TILE_N * 128];  // 64 x 64 bf16

        int w = tid >> 5, L = tid & 31;
        int mi = w & 3, ni = w >> 2;

        if (tid < TILE_N) s_cls[tid] = g_perm[cam * CAP + tile * TILE_N + tid];
        int ncs = g_samp_cnt[cam];
        int nch = max(1, (ncs + TILE_M - 1) / TILE_M);   // == 1 in practice
        __syncthreads();

        // B: row-contiguous mapping. col4 = tid&15, rows = (tid>>4) + 16j.
        int col4 = tid & 15;
        int rb   = tid >> 4;
        const float* bsrc[4];
        bool bcopy[4];
#pragma unroll
        for (int j = 0; j < 4; j++) {
            int row = rb + 16 * j;
            int cls = s_cls[row];
            bsrc[j] = mem + (size_t)(cls >= 0 ? cls : 0) * D_DIM + col4 * 4;
            bcopy[j] = (cls >= 0) && (g_is_label[cls >= 0 ? cls : 0] == 0);
        }
        const ptrdiff_t out_off = out_mem - mem;
        uint32_t sbso = sw128((uint32_t)(rb * 128 + col4 * 8));

        // A: 4 threads/row, 32B each (2x cp.async 16B)
        int arow = tid >> 2;
        int ach  = tid & 3;
        uint32_t saso = sw128((uint32_t)(arow * 128 + ach * 32));

        uint32_t smA_u[2] = { smem_u32(smA[0]), smem_u32(smA[1]) };
        uint32_t smB_u[2] = { smem_u32(smB[0]), smem_u32(smB[1]) };

        for (int mc = 0; mc < nch; mc++) {
            if (tid < TILE_M) {
                int m = mc * TILE_M + tid;
                int s = (m < ncs) ? g_samp[cam * B_SAMP + m] : -1;
                s_samp[tid] = s;
                s_lab[tid]  = (s >= 0) ? labels[s] : -1;
            }
            __syncthreads();
            int samp = s_samp[arow];
            const __nv_bfloat16* asrcg =
                g_featb + (size_t)(samp >= 0 ? samp : 0) * D_DIM + ach * 16;

            float acc[16];
#pragma unroll
            for (int i = 0; i < 16; i++) acc[i] = 0.f;

            // prologue: A(0) via cp.async, B(0) via regs
            cp_async16(smA_u[0] + saso, asrcg);
            cp_async16(smA_u[0] + (saso ^ 16u), asrcg + 8);
            cp_commit();
            float4 vb[4];
#pragma unroll
            for (int j = 0; j < 4; j++)
                vb[j] = *(const float4*)(bsrc[j]);

            bool do_copy = (mc == 0);
            float carry[4] = {0.f, 0.f, 0.f, 0.f};
            for (int kt = 0; kt < NKT; kt++) {
                int buf = kt & 1;
                // ---- STS B(kt) + carry-realigned fp32 copy-out
#pragma unroll
                for (int j = 0; j < 4; j++) {
                    float4 v = vb[j];
                    uint2 p2;
                    p2.x = bf2_bits(v.x, v.y);
                    p2.y = bf2_bits(v.z, v.w);
                    *(uint2*)(smB[buf] + sbso + (uint32_t)(j * 2048)) = p2;
                    if (do_copy) {
                        float up = __shfl_up_sync(0xffffffffu, v.w, 1);
                        float nc = __shfl_sync(0xffffffffu, v.w, L | 15);
                        if (bcopy[j]) {
                            float* dst = (float*)(bsrc[j] + out_off) + kt * TILE_K;
                            if (kt == 0 && col4 == 0) {
                                dst[0] = v.x; dst[1] = v.y; dst[2] = v.z;
                            } else {
                                float lead = (col4 == 0) ? carry[j] : up;
                                *(float4*)(dst - 1) = make_float4(lead, v.x, v.y, v.z);
                            }
                            if (kt == NKT - 1 && col4 == 15) dst[3] = v.w;
                        }
                        carry[j] = nc;
                    }
                }
                // ---- batched B prefetch (tight group just before barrier)
                if (kt < NKT - 1) {
                    int ko = (kt + 1) * TILE_K;
#pragma unroll
                    for (int j = 0; j < 4; j++)
                        vb[j] = *(const float4*)(bsrc[j] + ko);
                }
                cp_wait0();
                __syncthreads();
                // ---- A prefetch kt+1 (after barrier: smem WAR vs mma(kt-1))
                if (kt < NKT - 1) {
                    int ko = (kt + 1) * TILE_K;
                    cp_async16(smA_u[buf ^ 1] + saso, asrcg + ko);
                    cp_async16(smA_u[buf ^ 1] + (saso ^ 16u), asrcg + ko + 8);
                    cp_commit();
                }
                // ---- mma on smem[buf]: warp computes m16 x n32
                {
                    uint32_t arw = (uint32_t)(mi * 16 + (L & 15));
                    uint32_t kh  = (uint32_t)(L >> 4) * 16u;
#pragma unroll
                    for (int ks = 0; ks < 4; ks++) {
                        uint32_t acol = (uint32_t)(ks * 32) + kh;
                        uint32_t ao = sw128(arw * 128 + acol);
                        uint32_t a0, a1, a2, a3;
                        ldsm_x4(a0, a1, a2, a3, smA_u[buf] + ao);
#pragma unroll
                        for (int bh = 0; bh < 2; bh++) {
                            uint32_t brw = (uint32_t)(ni * 32 + bh * 16 + (L & 15));
                            uint32_t bo = sw128(brw * 128 + acol);
                            uint32_t b0, b1, b2, b3;
                            ldsm_x4(b0, b1, b2, b3, smB_u[buf] + bo);
                            float* aB = acc + bh * 8;
                            mma_bf16(aB[0], aB[1], aB[2], aB[3], a0, a1, a2, a3, b0, b2);
                            mma_bf16(aB[4], aB[5], aB[6], aB[7], a0, a1, a2, a3, b1, b3);
                        }
                    }
                }
            }

            // ---- epilogue: scale, exp, pos capture, row reduce (validated)
            {
                int rlo = mi * 16 + (L >> 2);
                int rhi = rlo + 8;
                int slo_s = s_samp[rlo], shi_s = s_samp[rhi];
                int llo = s_lab[rlo],    lhi = s_lab[rhi];
                float slo = 0.f, shi = 0.f;
#pragma unroll
                for (int t = 0; t < 4; t++) {
                    int cbase = ni * 32 + t * 8 + (L & 3) * 2;
#pragma unroll
                    for (int c = 0; c < 2; c++) {
                        int cls = s_cls[cbase + c];
                        if (cls >= 0) {
                            if (slo_s >= 0) {
                                float val = acc[t * 4 + c] * INV_TEMP;
                                slo += __expf(val);
                                if (cls == llo) g_pos[slo_s] = val;
                            }
                            if (shi_s >= 0) {
                                float val = acc[t * 4 + 2 + c] * INV_TEMP;
                                shi += __expf(val);
                                if (cls == lhi) g_pos[shi_s] = val;
                            }
                        }
                    }
                }
                slo += __shfl_xor_sync(0xffffffffu, slo, 1);
                slo += __shfl_xor_sync(0xffffffffu, slo, 2);
                shi += __shfl_xor_sync(0xffffffffu, shi, 1);
                shi += __shfl_xor_sync(0xffffffffu, shi, 2);
                if ((L & 3) == 0) {
                    if (slo_s >= 0) atomicAdd(&g_sumexp[slo_s], slo);
                    if (shi_s >= 0) atomicAdd(&g_sumexp[shi_s], shi);
                }
            }
            __syncthreads();
        }
    }

    // ---- completion signal; last tile-slot block computes the loss ----
    __threadfence();
    __shared__ int s_last;
    if (tid == 0) s_last = (atomicAdd(&g_done, 1) == GEMM_TILE_MAX - 1) ? 1 : 0;
    __syncthreads();
    if (s_last) {
        __threadfence();
        __shared__ float red[256];
        float v = (logf(g_sumexp[tid]) - g_pos[tid]) / (float)g_samp_cnt[cams[tid]];
        red[tid] = v;
        __syncthreads();
        for (int s = 128; s > 0; s >>= 1) {
            if (tid < s) red[tid] += red[tid + s];
            __syncthreads();
        }
        if (tid == 0) out_mem[-1] = red[0];   // out[0] = loss
    }
}

extern "C" void kernel_launch(void* const* d_in, const int* in_sizes, int n_in,
                              void* d_out, int out_size) {
    const float* features     = (const float*)d_in[0];
    const int*   labels       = (const int*)d_in[1];
    const int*   cams         = (const int*)d_in[2];
    const float* class_memory = (const float*)d_in[3];
    const int*   class_camera = (const int*)d_in[4];
    float* out = (float*)d_out;          // [0] = loss, [1..] = new_memory
    float* out_mem = out + 1;

    prep0_kernel<<<512, 256>>>(features, class_camera);                 // slot 0
    prep13_kernel<<<PREP_BLOCKS + 1, 256>>>(class_camera, cams, labels); // slot 1
    gemm_kernel<<<GEMM_BLOCKS, 256>>>(class_memory, labels, features, cams, out_mem); // slot 2
}